// round 3
// baseline (speedup 1.0000x reference)
#include <cuda_runtime.h>
#include <cstdint>
#include <math.h>

#define T_DIM 512
#define B_DIM 256
#define H_DIM 256
#define H3    768
#define M_TOT (T_DIM * B_DIM)

// Scratch for precomputed input gates gi = ins @ Wi + bi : [T*B, 3H] fp32 (402 MB)
__device__ float g_gi[(size_t)M_TOT * H3];

// ---------------------------------------------------------------------------
// Kernel 1: GI = ins @ Wi + bi    (M=131072, K=256, N=768)
// Tiles: BM=64, BN=64, BK=16, 256 threads, each thread computes 4x4.
// ---------------------------------------------------------------------------
__global__ __launch_bounds__(256) void gi_gemm(const float* __restrict__ A,
                                               const float* __restrict__ Wi,
                                               const float* __restrict__ bi) {
    const int BM = 64, BN = 64, BK = 16;
    __shared__ float As[BK][BM];   // transposed A tile: As[k][m]
    __shared__ float Bs[BK][BN];   // Bs[k][n]

    const int m0 = blockIdx.x * BM;
    const int n0 = blockIdx.y * BN;
    const int tid = threadIdx.x;
    const int tx = tid % 16;        // output col group (4 cols)
    const int ty = tid / 16;        // output row group (4 rows)

    // load mappings
    const int ar = tid >> 2;        // 0..63  A row
    const int ac = tid & 3;         // 0..3   A float4 col within BK
    const int br = tid >> 4;        // 0..15  B k-row
    const int bc = tid & 15;        // 0..15  B float4 col within BN

    float acc[4][4] = {};

    for (int k0 = 0; k0 < 256; k0 += BK) {
        float4 av = *(const float4*)&A[(size_t)(m0 + ar) * 256 + k0 + ac * 4];
        As[ac * 4 + 0][ar] = av.x;
        As[ac * 4 + 1][ar] = av.y;
        As[ac * 4 + 2][ar] = av.z;
        As[ac * 4 + 3][ar] = av.w;
        *(float4*)&Bs[br][bc * 4] =
            *(const float4*)&Wi[(size_t)(k0 + br) * H3 + n0 + bc * 4];
        __syncthreads();

        #pragma unroll
        for (int k = 0; k < BK; k++) {
            float4 a = *(const float4*)&As[k][ty * 4];
            float4 b = *(const float4*)&Bs[k][tx * 4];
            acc[0][0] += a.x * b.x; acc[0][1] += a.x * b.y; acc[0][2] += a.x * b.z; acc[0][3] += a.x * b.w;
            acc[1][0] += a.y * b.x; acc[1][1] += a.y * b.y; acc[1][2] += a.y * b.z; acc[1][3] += a.y * b.w;
            acc[2][0] += a.z * b.x; acc[2][1] += a.z * b.y; acc[2][2] += a.z * b.z; acc[2][3] += a.z * b.w;
            acc[3][0] += a.w * b.x; acc[3][1] += a.w * b.y; acc[3][2] += a.w * b.z; acc[3][3] += a.w * b.w;
        }
        __syncthreads();
    }

    float4 bb = *(const float4*)&bi[n0 + tx * 4];
    #pragma unroll
    for (int i = 0; i < 4; i++) {
        const size_t row = (size_t)(m0 + ty * 4 + i);
        float4 o;
        o.x = acc[i][0] + bb.x;
        o.y = acc[i][1] + bb.y;
        o.z = acc[i][2] + bb.z;
        o.w = acc[i][3] + bb.w;
        *(float4*)&g_gi[row * H3 + n0 + tx * 4] = o;
    }
}

// ---------------------------------------------------------------------------
// Kernel 2: one GRU step, fused gh-GEMM + gate math.
//   gh = h_masked @ Wh ; r=sig(gi_r+gh_r); z=sig(gi_z+gh_z)
//   n=tanh(gi_n + r*(gh_n+bhn)); h' = (1-z)*n + z*h_masked
// Grid: (B/32, H/16) = 128 CTAs, 128 threads. Thread: 4 batch rows x 1 col x 3 gates.
// resets is int32 (jax bool promoted by the harness).
// ---------------------------------------------------------------------------
__global__ __launch_bounds__(128) void gru_step(
    const float* __restrict__ h_prev,           // [B,H] (= y[t-1] or carry)
    const int* __restrict__ resets_t,           // [B] int32 bool
    const float* __restrict__ Wh,               // [H, 3H]
    const float* __restrict__ bhn,              // [H]
    float* __restrict__ h_out,                  // [B,H] (= y[t])
    int t)
{
    const int BM = 32, BN = 16, BK = 32;
    __shared__ float hs[BM][BK];        // hs[b][k], masked
    __shared__ float ws[3][BK][BN];     // per-gate Wh tiles

    const int b0 = blockIdx.x * BM;
    const int n0 = blockIdx.y * BN;
    const int tid = threadIdx.x;
    const int tn = tid & 15;            // 0..15 output col
    const int tb = tid >> 4;            // 0..7  output row group (4 rows)

    // load mapping
    const int lr = tid >> 2;            // 0..31
    const int lc = tid & 3;             // 0..3

    const bool my_reset = resets_t[b0 + lr] != 0;

    float ar[4] = {}, az[4] = {}, an[4] = {};

    for (int k0 = 0; k0 < H_DIM; k0 += BK) {
        // h tile (reset-masked), 2 float4 per thread
        #pragma unroll
        for (int kc = 0; kc < 2; kc++) {
            const int kk = (lc + kc * 4) * 4;   // 0..28, step 4
            float4 v;
            if (my_reset) {
                v = make_float4(0.f, 0.f, 0.f, 0.f);
            } else {
                v = *(const float4*)&h_prev[(size_t)(b0 + lr) * H_DIM + k0 + kk];
            }
            *(float4*)&hs[lr][kk] = v;
        }
        // Wh tiles: one float4 per thread per gate
        #pragma unroll
        for (int g = 0; g < 3; g++) {
            *(float4*)&ws[g][lr][lc * 4] =
                *(const float4*)&Wh[(size_t)(k0 + lr) * H3 + g * H_DIM + n0 + lc * 4];
        }
        __syncthreads();

        #pragma unroll
        for (int k = 0; k < BK; k++) {
            const float wr = ws[0][k][tn];
            const float wz = ws[1][k][tn];
            const float wn = ws[2][k][tn];
            #pragma unroll
            for (int i = 0; i < 4; i++) {
                const float hv = hs[tb * 4 + i][k];
                ar[i] += hv * wr;
                az[i] += hv * wz;
                an[i] += hv * wn;
            }
        }
        __syncthreads();
    }

    const int j = n0 + tn;
    const float bn_j = bhn[j];
    #pragma unroll
    for (int i = 0; i < 4; i++) {
        const int b = b0 + tb * 4 + i;
        const bool rst = resets_t[b] != 0;
        const size_t gbase = ((size_t)(t * B_DIM + b)) * H3 + j;
        const float gi_r = g_gi[gbase];
        const float gi_z = g_gi[gbase + H_DIM];
        const float gi_n = g_gi[gbase + 2 * H_DIM];
        const float hp = rst ? 0.f : h_prev[(size_t)b * H_DIM + j];

        const float r = 1.f / (1.f + expf(-(gi_r + ar[i])));
        const float z = 1.f / (1.f + expf(-(gi_z + az[i])));
        const float n = tanhf(gi_n + r * (an[i] + bn_j));
        h_out[(size_t)b * H_DIM + j] = (1.f - z) * n + z * hp;
    }
}

// ---------------------------------------------------------------------------
extern "C" void kernel_launch(void* const* d_in, const int* in_sizes, int n_in,
                              void* d_out, int out_size) {
    const float* ins    = (const float*)d_in[0];   // [T,B,H]
    const int*   resets = (const int*)d_in[1];     // [T,B] int32 (bool promoted)
    const float* carry  = (const float*)d_in[2];   // [B,H]
    const float* Wi     = (const float*)d_in[3];   // [H,3H]
    const float* bi     = (const float*)d_in[4];   // [3H]
    const float* Wh     = (const float*)d_in[5];   // [H,3H]
    const float* bhn    = (const float*)d_in[6];   // [H]
    float*       out    = (float*)d_out;           // [T,B,H]

    // Phase 1: precompute all input gates (parallel over T*B)
    dim3 g1(M_TOT / 64, H3 / 64);
    gi_gemm<<<g1, 256>>>(ins, Wi, bi);

    // Phase 2: sequential scan, one fused kernel per step
    dim3 g2(B_DIM / 32, H_DIM / 16);
    for (int t = 0; t < T_DIM; t++) {
        const float* hp = (t == 0) ? carry : (out + (size_t)(t - 1) * B_DIM * H_DIM);
        gru_step<<<g2, 128>>>(hp,
                              resets + (size_t)t * B_DIM,
                              Wh, bhn,
                              out + (size_t)t * B_DIM * H_DIM,
                              t);
    }
}